// round 4
// baseline (speedup 1.0000x reference)
#include <cuda_runtime.h>

// ResLSTM on GB300: warp = 8 batches (NB=8), lane = hidden unit j.
// Weight quads loaded once per 4-row group, reused by 8 batches
// (crossbar 24 cyc / 64 fma2 = 0.375 cyc/fma2 -> fma-bound).
// Per-timestep state (o0, o1, h) lives in per-warp SMEM, not registers,
// so we stay under the register cap (R3 lesson: NB=8 in regs spills).

#define WARPS   8
#define NT      (WARPS * 32)
#define NB      8
#define B_TOTAL 131072
#define TT      5
#define NF      62

typedef unsigned long long ull;

// ---- shared layout (floats) ----
#define OFF_WI0 0                     // 64*128 (rows 62,63 zero-padded)
#define OFF_WH0 (OFF_WI0 + 64*128)    // 32*128
#define OFF_W1  (OFF_WH0 + 32*128)    // 64*128 (rows 0..31 = w_ih1, 32..63 = w_hh1)
#define OFF_B0  (OFF_W1  + 64*128)    // 128  (interleaved j*4+g)
#define OFF_B1  (OFF_B0 + 128)        // 128
#define OFF_G0  (OFF_B1 + 128)        // 160
#define OFF_BE0 (OFF_G0 + 160)        // 160
#define OFF_G1  (OFF_BE0 + 160)       // 160
#define OFF_BE1 (OFF_G1 + 160)        // 160
#define OFF_DW  (OFF_BE1 + 160)       // 480
#define OFF_DB  (OFF_DW + 480)        // 4
#define OFF_SCR (OFF_DB + 4)
// per-warp scratch (floats):
//   [0..1279]    XO1 : layer0 X as [bi*64+n] (512 used), then layer1 O1 as [t*256+bi*32+j]
//   [1280..1535] H   : [bi*32+k]
//   [1536..2815] O0  : [t*256+bi*32+j]
#define SCR_PER_WARP 2816
#define SMEM_FLOATS (OFF_SCR + WARPS * SCR_PER_WARP)
#define SMEM_BYTES  (SMEM_FLOATS * 4)

__device__ __forceinline__ float tanh_f(float x) {
    float y;
    asm("tanh.approx.f32 %0, %1;" : "=f"(y) : "f"(x));
    return y;
}
__device__ __forceinline__ float sigm(float x) {
    return fmaf(0.5f, tanh_f(0.5f * x), 0.5f);
}
__device__ __forceinline__ float lrelu(float x) {
    return x > 0.0f ? x : 0.01f * x;
}
__device__ __forceinline__ ull pk2(float x) {
    ull r; asm("mov.b64 %0, {%1, %2};" : "=l"(r) : "f"(x), "f"(x)); return r;
}
__device__ __forceinline__ void fma2(ull& d, ull a, ull b) {
    asm("fma.rn.f32x2 %0, %1, %2, %0;" : "+l"(d) : "l"(a), "l"(b));
}
__device__ __forceinline__ void unpk(ull v, float& lo, float& hi) {
    asm("mov.b64 {%0, %1}, %2;" : "=f"(lo), "=f"(hi) : "l"(v));
}

// rows r4..r4+3 of W (layout [r][lane*4+g]); operand vec read as broadcast
// float4 from per-warp scratch; NB batches reuse the 4 weight quads.
__device__ __forceinline__ void gemv_group(
    const float* __restrict__ W, const float* __restrict__ vec, int vstride,
    int r4, int lane, ull a01[NB], ull a23[NB])
{
    const ulonglong2* w = (const ulonglong2*)(W + r4 * 128) + lane;
    ulonglong2 w0 = w[0];
    ulonglong2 w1 = w[32];
    ulonglong2 w2 = w[64];
    ulonglong2 w3 = w[96];
#pragma unroll
    for (int bi = 0; bi < NB; bi++) {
        float4 xv = *(const float4*)(vec + bi * vstride + r4);
        ull xp;
        xp = pk2(xv.x); fma2(a01[bi], xp, w0.x); fma2(a23[bi], xp, w0.y);
        xp = pk2(xv.y); fma2(a01[bi], xp, w1.x); fma2(a23[bi], xp, w1.y);
        xp = pk2(xv.z); fma2(a01[bi], xp, w2.x); fma2(a23[bi], xp, w2.y);
        xp = pk2(xv.w); fma2(a01[bi], xp, w3.x); fma2(a23[bi], xp, w3.y);
    }
}

__global__ __launch_bounds__(NT, 1) void reslstm_kernel(
    const float* __restrict__ data,
    const float* __restrict__ w_ih0, const float* __restrict__ w_hh0,
    const float* __restrict__ b_ih0, const float* __restrict__ b_hh0,
    const float* __restrict__ g0,    const float* __restrict__ be0,
    const float* __restrict__ w_ih1, const float* __restrict__ w_hh1,
    const float* __restrict__ b_ih1, const float* __restrict__ b_hh1,
    const float* __restrict__ g1,    const float* __restrict__ be1,
    const float* __restrict__ dw,    const float* __restrict__ db,
    float* __restrict__ out)
{
    extern __shared__ float sm[];
    float* sWI0 = sm + OFF_WI0;
    float* sWH0 = sm + OFF_WH0;
    float* sW1  = sm + OFF_W1;
    float* sB0  = sm + OFF_B0;
    float* sB1  = sm + OFF_B1;
    float* sG0  = sm + OFF_G0;
    float* sBe0 = sm + OFF_BE0;
    float* sG1  = sm + OFF_G1;
    float* sBe1 = sm + OFF_BE1;
    float* sDW  = sm + OFF_DW;
    float* sDB  = sm + OFF_DB;

    const int tid  = threadIdx.x;
    const int lane = tid & 31;
    const int wid  = tid >> 5;

    // ---- stage weights, transposed+interleaved: [row][j*4+g] ----
    for (int i = tid; i < 64 * 128; i += NT) {
        int n = i >> 7, rem = i & 127, j = rem >> 2, g = rem & 3;
        sWI0[i] = (n < NF) ? w_ih0[(g * 32 + j) * NF + n] : 0.0f;
        sW1[i] = (n < 32) ? w_ih1[(g * 32 + j) * 32 + n]
                          : w_hh1[(g * 32 + j) * 32 + (n - 32)];
    }
    for (int i = tid; i < 32 * 128; i += NT) {
        int k = i >> 7, rem = i & 127, j = rem >> 2, g = rem & 3;
        sWH0[i] = w_hh0[(g * 32 + j) * 32 + k];
    }
    for (int i = tid; i < 128; i += NT) {
        int j = i >> 2, g = i & 3;
        sB0[i] = b_ih0[g * 32 + j] + b_hh0[g * 32 + j];
        sB1[i] = b_ih1[g * 32 + j] + b_hh1[g * 32 + j];
    }
    for (int i = tid; i < 160; i += NT) {
        sG0[i] = g0[i]; sBe0[i] = be0[i];
        sG1[i] = g1[i]; sBe1[i] = be1[i];
    }
    for (int i = tid; i < 480; i += NT) sDW[i] = dw[i];
    if (tid < 3) sDB[tid] = db[tid];

    float* scrXO1 = sm + OFF_SCR + wid * SCR_PER_WARP; // X: [bi*64+n] / O1: [t*256+bi*32+j]
    float* scrH   = scrXO1 + 1280;                     // [bi*32+k]
    float* scrO0  = scrH + 256;                        // [t*256+bi*32+j]

    // zero X pad (n=62,63) and h slots (initial h0 = 0)
    if (lane < NB) {
        scrXO1[lane * 64 + 62] = 0.0f;
        scrXO1[lane * 64 + 63] = 0.0f;
    }
#pragma unroll
    for (int bi = 0; bi < NB; bi++) scrH[bi * 32 + lane] = 0.0f;

    __syncthreads();

    const long long base = ((long long)blockIdx.x * WARPS + wid) * NB;
    const unsigned FULL = 0xffffffffu;

    ulonglong2 b0p = ((const ulonglong2*)sB0)[lane];
    ulonglong2 b1p = ((const ulonglong2*)sB1)[lane];

    float c0[NB];
#pragma unroll
    for (int bi = 0; bi < NB; bi++) c0[bi] = 0.f;

    // ================= layer 0 =================
#pragma unroll
    for (int t = 0; t < TT; t++) {
        // stage x[t] for NB batches
#pragma unroll
        for (int bi = 0; bi < NB; bi++) {
            const float* dp = data + (base + bi) * (NF * TT);
            scrXO1[bi * 64 + lane] = __ldg(dp + lane * TT + t);
            if (lane < NF - 32)
                scrXO1[bi * 64 + 32 + lane] = __ldg(dp + (lane + 32) * TT + t);
        }
        __syncwarp();

        ull a01[NB], a23[NB];
#pragma unroll
        for (int bi = 0; bi < NB; bi++) { a01[bi] = b0p.x; a23[bi] = b0p.y; }

#pragma unroll
        for (int r4 = 0; r4 < 64; r4 += 4)
            gemv_group(sWI0, scrXO1, 64, r4, lane, a01, a23);
#pragma unroll
        for (int r4 = 0; r4 < 32; r4 += 4)
            gemv_group(sWH0, scrH, 32, r4, lane, a01, a23);

        __syncwarp();
#pragma unroll
        for (int bi = 0; bi < NB; bi++) {
            float ai, af, ag, ao;
            unpk(a01[bi], ai, af);
            unpk(a23[bi], ag, ao);
            float ig = sigm(ai), fg = sigm(af);
            float gg = tanh_f(ag), og = sigm(ao);
            c0[bi] = fg * c0[bi] + ig * gg;
            float h = og * tanh_f(c0[bi]);
            scrH[bi * 32 + lane] = h;
            scrO0[t * 256 + bi * 32 + lane] = h;
        }
        __syncwarp();
    }

    // ---- LN0 + LeakyReLU (in-place on scrO0) ----
#pragma unroll
    for (int bi = 0; bi < NB; bi++) {
        float v[TT];
        float s = 0.f, sq = 0.f;
#pragma unroll
        for (int t = 0; t < TT; t++) {
            v[t] = scrO0[t * 256 + bi * 32 + lane];
            s += v[t]; sq += v[t] * v[t];
        }
#pragma unroll
        for (int off = 16; off > 0; off >>= 1) {
            s  += __shfl_xor_sync(FULL, s,  off);
            sq += __shfl_xor_sync(FULL, sq, off);
        }
        float mu  = s * (1.0f / 160.0f);
        float var = sq * (1.0f / 160.0f) - mu * mu;
        float rs  = rsqrtf(var + 1e-5f);
#pragma unroll
        for (int t = 0; t < TT; t++) {
            float y = (v[t] - mu) * rs * sG0[t * 32 + lane] + sBe0[t * 32 + lane];
            scrO0[t * 256 + bi * 32 + lane] = lrelu(y);
        }
    }

    // re-zero h slots for layer 1
#pragma unroll
    for (int bi = 0; bi < NB; bi++) scrH[bi * 32 + lane] = 0.0f;
    __syncwarp();

    // ================= layer 1 =================
    float c1[NB];
#pragma unroll
    for (int bi = 0; bi < NB; bi++) c1[bi] = 0.f;

#pragma unroll
    for (int t = 0; t < TT; t++) {
        ull a01[NB], a23[NB];
#pragma unroll
        for (int bi = 0; bi < NB; bi++) { a01[bi] = b1p.x; a23[bi] = b1p.y; }

        // input half: rows 0..31 of sW1 against o0[t]
#pragma unroll
        for (int r4 = 0; r4 < 32; r4 += 4)
            gemv_group(sW1, scrO0 + t * 256, 32, r4, lane, a01, a23);
        // recurrent half: rows 32..63 of sW1 against h1
#pragma unroll
        for (int r4 = 0; r4 < 32; r4 += 4)
            gemv_group(sW1 + 32 * 128, scrH, 32, r4, lane, a01, a23);

        __syncwarp();
#pragma unroll
        for (int bi = 0; bi < NB; bi++) {
            float ai, af, ag, ao;
            unpk(a01[bi], ai, af);
            unpk(a23[bi], ag, ao);
            float ig = sigm(ai), fg = sigm(af);
            float gg = tanh_f(ag), og = sigm(ao);
            c1[bi] = fg * c1[bi] + ig * gg;
            float h = og * tanh_f(c1[bi]);
            scrH[bi * 32 + lane] = h;
            scrXO1[t * 256 + bi * 32 + lane] = h;   // O1 region (X is dead)
        }
        __syncwarp();
    }

    // ---- LN1 + LeakyReLU + residual; head fused per batch ----
#pragma unroll
    for (int bi = 0; bi < NB; bi++) {
        float v[TT];
        float s = 0.f, sq = 0.f;
#pragma unroll
        for (int t = 0; t < TT; t++) {
            v[t] = scrXO1[t * 256 + bi * 32 + lane];
            s += v[t]; sq += v[t] * v[t];
        }
#pragma unroll
        for (int off = 16; off > 0; off >>= 1) {
            s  += __shfl_xor_sync(FULL, s,  off);
            sq += __shfl_xor_sync(FULL, sq, off);
        }
        float mu  = s * (1.0f / 160.0f);
        float var = sq * (1.0f / 160.0f) - mu * mu;
        float rs  = rsqrtf(var + 1e-5f);

        float p0 = 0.f, p1 = 0.f, p2 = 0.f;
#pragma unroll
        for (int t = 0; t < TT; t++) {
            int idx = t * 32 + lane;
            float y = (v[t] - mu) * rs * sG1[idx] + sBe1[idx];
            float o = lrelu(y) + scrO0[t * 256 + bi * 32 + lane];
            p0 += o * sDW[idx];
            p1 += o * sDW[160 + idx];
            p2 += o * sDW[320 + idx];
        }
#pragma unroll
        for (int off = 16; off > 0; off >>= 1) {
            p0 += __shfl_xor_sync(FULL, p0, off);
            p1 += __shfl_xor_sync(FULL, p1, off);
            p2 += __shfl_xor_sync(FULL, p2, off);
        }
        if (lane < 3) {
            float pv = (lane == 0) ? p0 : ((lane == 1) ? p1 : p2);
            pv += sDB[lane];
            out[(base + bi) * 3 + lane] = lrelu(pv);
        }
    }
}

extern "C" void kernel_launch(void* const* d_in, const int* in_sizes, int n_in,
                              void* d_out, int out_size) {
    const float* data  = (const float*)d_in[0];
    const float* w_ih0 = (const float*)d_in[1];
    const float* w_hh0 = (const float*)d_in[2];
    const float* b_ih0 = (const float*)d_in[3];
    const float* b_hh0 = (const float*)d_in[4];
    const float* g0    = (const float*)d_in[5];
    const float* be0   = (const float*)d_in[6];
    const float* w_ih1 = (const float*)d_in[7];
    const float* w_hh1 = (const float*)d_in[8];
    const float* b_ih1 = (const float*)d_in[9];
    const float* b_hh1 = (const float*)d_in[10];
    const float* g1    = (const float*)d_in[11];
    const float* be1   = (const float*)d_in[12];
    const float* dw    = (const float*)d_in[13];
    const float* db    = (const float*)d_in[14];
    float* out = (float*)d_out;

    cudaFuncSetAttribute(reslstm_kernel,
                         cudaFuncAttributeMaxDynamicSharedMemorySize, SMEM_BYTES);

    int grid = B_TOTAL / (WARPS * NB);   // 2048
    reslstm_kernel<<<grid, NT, SMEM_BYTES>>>(
        data, w_ih0, w_hh0, b_ih0, b_hh0, g0, be0,
        w_ih1, w_hh1, b_ih1, b_hh1, g1, be1, dw, db, out);
}

// round 5
// speedup vs baseline: 1.2193x; 1.2193x over previous
#include <cuda_runtime.h>

// ResLSTM on GB300, round 5 structure:
//  - warp = 4 batches (NB=4), lane = hidden unit j
//  - INPUT gemvs (no recurrence) are hoisted out of the t-loop: weight quads
//    streamed from L2 (pre-transposed __device__ arrays) and reused from
//    registers across 5 timesteps x 4 batches (crossbar/fma2: 0.625 -> 0.225)
//  - RECURRENT gemvs keep weights in smem (latency-critical path)
//  - smem/CTA ~66KB -> 3 CTAs/SM x 4 warps = 12 warps/SM, regs capped at 170

#define NT      128
#define NWARP   4
#define NB      4
#define B_TOTAL 131072
#define TT      5
#define NF      62

typedef unsigned long long ull;

// pre-transposed input weights: [row][j*4+g], 16B-aligned quads per (row,lane)
__device__ __align__(16) float g_WI0T[64 * 128];   // rows 62,63 zero-padded
__device__ __align__(16) float g_WI1T[32 * 128];

// ---- shared layout (floats) ----
#define OFF_WH0 0                      // 32*128 recurrent L0
#define OFF_W1R (OFF_WH0 + 32*128)     // 32*128 recurrent L1
#define OFF_B0  (OFF_W1R + 32*128)     // 128 (interleaved j*4+g)
#define OFF_B1  (OFF_B0 + 128)
#define OFF_G0  (OFF_B1 + 128)
#define OFF_BE0 (OFF_G0 + 160)
#define OFF_G1  (OFF_BE0 + 160)
#define OFF_BE1 (OFF_G1 + 160)
#define OFF_DW  (OFF_BE1 + 160)        // 480
#define OFF_DB  (OFF_DW + 480)         // 4
#define OFF_SCR (OFF_DB + 4)
// per-warp scratch: X [bi][t][64] = 1280 | H [bi][32] = 128 | O0 [t][bi][32] = 640
#define SCR_W   2048
#define SMEM_FLOATS (OFF_SCR + NWARP * SCR_W)
#define SMEM_BYTES  (SMEM_FLOATS * 4)

__device__ __forceinline__ float tanh_f(float x) {
    float y; asm("tanh.approx.f32 %0, %1;" : "=f"(y) : "f"(x)); return y;
}
__device__ __forceinline__ float sigm(float x) {
    return fmaf(0.5f, tanh_f(0.5f * x), 0.5f);
}
__device__ __forceinline__ float lrelu(float x) {
    return x > 0.0f ? x : 0.01f * x;
}
__device__ __forceinline__ ull pk2(float x) {
    ull r; asm("mov.b64 %0, {%1, %2};" : "=l"(r) : "f"(x), "f"(x)); return r;
}
__device__ __forceinline__ void fma2(ull& d, ull a, ull b) {
    asm("fma.rn.f32x2 %0, %1, %2, %0;" : "+l"(d) : "l"(a), "l"(b));
}
__device__ __forceinline__ void unpk(ull v, float& lo, float& hi) {
    asm("mov.b64 {%0, %1}, %2;" : "=f"(lo), "=f"(hi) : "l"(v));
}

// ---------------- prep: transpose input weights into L2-friendly layout ----
__global__ void prep_kernel(const float* __restrict__ w_ih0,
                            const float* __restrict__ w_ih1) {
    for (int i = blockIdx.x * blockDim.x + threadIdx.x; i < 64 * 128;
         i += blockDim.x * gridDim.x) {
        int n = i >> 7, rem = i & 127, j = rem >> 2, g = rem & 3;
        g_WI0T[i] = (n < NF) ? w_ih0[(g * 32 + j) * NF + n] : 0.0f;
        if (n < 32) g_WI1T[i] = w_ih1[(g * 32 + j) * 32 + n];
    }
}

// input-phase: stream nG weight groups once, reuse across (t, bi) from regs
__device__ __forceinline__ void phaseA(
    const float* __restrict__ Wg, const float* __restrict__ vec,
    int bistride, int tstride, int nG, int lane,
    ull xg01[TT][NB], ull xg23[TT][NB])
{
#pragma unroll 1
    for (int g = 0; g < nG; g++) {
        const ulonglong2* w = (const ulonglong2*)(Wg + g * 512) + lane;
        ulonglong2 w0 = w[0], w1 = w[32], w2 = w[64], w3 = w[96];
        const float* vg = vec + g * 4;
#pragma unroll
        for (int t = 0; t < TT; t++) {
#pragma unroll
            for (int bi = 0; bi < NB; bi++) {
                float4 xv = *(const float4*)(vg + bi * bistride + t * tstride);
                ull xp;
                xp = pk2(xv.x); fma2(xg01[t][bi], xp, w0.x); fma2(xg23[t][bi], xp, w0.y);
                xp = pk2(xv.y); fma2(xg01[t][bi], xp, w1.x); fma2(xg23[t][bi], xp, w1.y);
                xp = pk2(xv.z); fma2(xg01[t][bi], xp, w2.x); fma2(xg23[t][bi], xp, w2.y);
                xp = pk2(xv.w); fma2(xg01[t][bi], xp, w3.x); fma2(xg23[t][bi], xp, w3.y);
            }
        }
    }
}

// recurrent-phase: one 4-row group from smem weights against h (per-warp smem)
__device__ __forceinline__ void phaseB_group(
    const float* __restrict__ Wsm, const float* __restrict__ hvec,
    int g, int lane, ull a01[NB], ull a23[NB])
{
    const ulonglong2* w = (const ulonglong2*)(Wsm + g * 512) + lane;
    ulonglong2 w0 = w[0], w1 = w[32], w2 = w[64], w3 = w[96];
#pragma unroll
    for (int bi = 0; bi < NB; bi++) {
        float4 hv = *(const float4*)(hvec + bi * 32 + g * 4);
        ull xp;
        xp = pk2(hv.x); fma2(a01[bi], xp, w0.x); fma2(a23[bi], xp, w0.y);
        xp = pk2(hv.y); fma2(a01[bi], xp, w1.x); fma2(a23[bi], xp, w1.y);
        xp = pk2(hv.z); fma2(a01[bi], xp, w2.x); fma2(a23[bi], xp, w2.y);
        xp = pk2(hv.w); fma2(a01[bi], xp, w3.x); fma2(a23[bi], xp, w3.y);
    }
}

__global__ __launch_bounds__(NT, 3) void reslstm_kernel(
    const float* __restrict__ data,
    const float* __restrict__ w_hh0,
    const float* __restrict__ b_ih0, const float* __restrict__ b_hh0,
    const float* __restrict__ g0,    const float* __restrict__ be0,
    const float* __restrict__ w_hh1,
    const float* __restrict__ b_ih1, const float* __restrict__ b_hh1,
    const float* __restrict__ g1,    const float* __restrict__ be1,
    const float* __restrict__ dw,    const float* __restrict__ db,
    float* __restrict__ out)
{
    extern __shared__ float sm[];
    float* sWH0 = sm + OFF_WH0;
    float* sW1R = sm + OFF_W1R;
    float* sB0  = sm + OFF_B0;
    float* sB1  = sm + OFF_B1;
    float* sG0  = sm + OFF_G0;
    float* sBe0 = sm + OFF_BE0;
    float* sG1  = sm + OFF_G1;
    float* sBe1 = sm + OFF_BE1;
    float* sDW  = sm + OFF_DW;
    float* sDB  = sm + OFF_DB;

    const int tid  = threadIdx.x;
    const int lane = tid & 31;
    const int wid  = tid >> 5;

    // stage recurrent weights transposed+interleaved [k][j*4+g]
    for (int i = tid; i < 32 * 128; i += NT) {
        int k = i >> 7, rem = i & 127, j = rem >> 2, g = rem & 3;
        sWH0[i] = w_hh0[(g * 32 + j) * 32 + k];
        sW1R[i] = w_hh1[(g * 32 + j) * 32 + k];
    }
    for (int i = tid; i < 128; i += NT) {
        int j = i >> 2, g = i & 3;
        sB0[i] = b_ih0[g * 32 + j] + b_hh0[g * 32 + j];
        sB1[i] = b_ih1[g * 32 + j] + b_hh1[g * 32 + j];
    }
    for (int i = tid; i < 160; i += NT) {
        sG0[i] = g0[i]; sBe0[i] = be0[i];
        sG1[i] = g1[i]; sBe1[i] = be1[i];
    }
    for (int i = tid; i < 480; i += NT) sDW[i] = dw[i];
    if (tid < 3) sDB[tid] = db[tid];

    float* scrX  = sm + OFF_SCR + wid * SCR_W;  // [bi*320 + t*64 + n]
    float* scrH  = scrX + 1280;                 // [bi*32 + k]
    float* scrO0 = scrH + 128;                  // [t*128 + bi*32 + j]

    const long long base = ((long long)blockIdx.x * NWARP + wid) * NB;

    // stage X for all t (pad n=62,63 with 0); init h=0
#pragma unroll
    for (int bi = 0; bi < NB; bi++) {
        const float* dp = data + (base + bi) * (NF * TT);
#pragma unroll
        for (int t = 0; t < TT; t++) {
            scrX[bi * 320 + t * 64 + lane] = __ldg(dp + lane * TT + t);
            if (lane < NF - 32)
                scrX[bi * 320 + t * 64 + 32 + lane] = __ldg(dp + (lane + 32) * TT + t);
        }
        if (lane < 2) {
#pragma unroll
            for (int t = 0; t < TT; t++)
                scrX[bi * 320 + t * 64 + 62 + lane] = 0.0f;
        }
        scrH[bi * 32 + lane] = 0.0f;
    }
    __syncthreads();

    const unsigned FULL = 0xffffffffu;
    ulonglong2 b0p = ((const ulonglong2*)sB0)[lane];
    ulonglong2 b1p = ((const ulonglong2*)sB1)[lane];

    // ======== layer 0: input phase (hoisted over t) ========
    ull xg01[TT][NB], xg23[TT][NB];
#pragma unroll
    for (int t = 0; t < TT; t++)
#pragma unroll
        for (int bi = 0; bi < NB; bi++) { xg01[t][bi] = b0p.x; xg23[t][bi] = b0p.y; }

    phaseA(g_WI0T, scrX, 320, 64, 16, lane, xg01, xg23);

    // ======== layer 0: recurrent phase ========
    float c0[NB];
#pragma unroll
    for (int bi = 0; bi < NB; bi++) c0[bi] = 0.f;

#pragma unroll
    for (int t = 0; t < TT; t++) {
#pragma unroll 1
        for (int g = 0; g < 8; g++)
            phaseB_group(sWH0, scrH, g, lane, xg01[t], xg23[t]);
#pragma unroll
        for (int bi = 0; bi < NB; bi++) {
            float ai, af, ag, ao;
            unpk(xg01[t][bi], ai, af);
            unpk(xg23[t][bi], ag, ao);
            float ig = sigm(ai), fg = sigm(af);
            float gg = tanh_f(ag), og = sigm(ao);
            c0[bi] = fg * c0[bi] + ig * gg;
            float h = og * tanh_f(c0[bi]);
            scrH[bi * 32 + lane] = h;
            scrO0[t * 128 + bi * 32 + lane] = h;
        }
        __syncwarp();
    }

    // ---- LN0 + LeakyReLU (in place in scrO0) ----
#pragma unroll
    for (int bi = 0; bi < NB; bi++) {
        float v[TT];
        float s = 0.f, sq = 0.f;
#pragma unroll
        for (int t = 0; t < TT; t++) {
            v[t] = scrO0[t * 128 + bi * 32 + lane];
            s += v[t]; sq += v[t] * v[t];
        }
#pragma unroll
        for (int off = 16; off > 0; off >>= 1) {
            s  += __shfl_xor_sync(FULL, s,  off);
            sq += __shfl_xor_sync(FULL, sq, off);
        }
        float mu  = s * (1.0f / 160.0f);
        float var = sq * (1.0f / 160.0f) - mu * mu;
        float rs  = rsqrtf(var + 1e-5f);
#pragma unroll
        for (int t = 0; t < TT; t++) {
            float y = (v[t] - mu) * rs * sG0[t * 32 + lane] + sBe0[t * 32 + lane];
            scrO0[t * 128 + bi * 32 + lane] = lrelu(y);
        }
        scrH[bi * 32 + lane] = 0.0f;   // reset h for layer 1
    }
    __syncwarp();

    // ======== layer 1: input phase (over post-LN o0, hoisted over t) ========
#pragma unroll
    for (int t = 0; t < TT; t++)
#pragma unroll
        for (int bi = 0; bi < NB; bi++) { xg01[t][bi] = b1p.x; xg23[t][bi] = b1p.y; }

    phaseA(g_WI1T, scrO0, 32, 128, 8, lane, xg01, xg23);

    // ======== layer 1: recurrent phase ========
    float c1[NB];
    float o1[TT][NB];
#pragma unroll
    for (int bi = 0; bi < NB; bi++) c1[bi] = 0.f;

#pragma unroll
    for (int t = 0; t < TT; t++) {
#pragma unroll 1
        for (int g = 0; g < 8; g++)
            phaseB_group(sW1R, scrH, g, lane, xg01[t], xg23[t]);
#pragma unroll
        for (int bi = 0; bi < NB; bi++) {
            float ai, af, ag, ao;
            unpk(xg01[t][bi], ai, af);
            unpk(xg23[t][bi], ag, ao);
            float ig = sigm(ai), fg = sigm(af);
            float gg = tanh_f(ag), og = sigm(ao);
            c1[bi] = fg * c1[bi] + ig * gg;
            float h = og * tanh_f(c1[bi]);
            o1[t][bi] = h;
            scrH[bi * 32 + lane] = h;
        }
        __syncwarp();
    }

    // ---- LN1 + LeakyReLU + residual + head ----
#pragma unroll
    for (int bi = 0; bi < NB; bi++) {
        float s = 0.f, sq = 0.f;
#pragma unroll
        for (int t = 0; t < TT; t++) {
            float v = o1[t][bi];
            s += v; sq += v * v;
        }
#pragma unroll
        for (int off = 16; off > 0; off >>= 1) {
            s  += __shfl_xor_sync(FULL, s,  off);
            sq += __shfl_xor_sync(FULL, sq, off);
        }
        float mu  = s * (1.0f / 160.0f);
        float var = sq * (1.0f / 160.0f) - mu * mu;
        float rs  = rsqrtf(var + 1e-5f);

        float p0 = 0.f, p1 = 0.f, p2 = 0.f;
#pragma unroll
        for (int t = 0; t < TT; t++) {
            int idx = t * 32 + lane;
            float y = (o1[t][bi] - mu) * rs * sG1[idx] + sBe1[idx];
            float o = lrelu(y) + scrO0[t * 128 + bi * 32 + lane];
            p0 += o * sDW[idx];
            p1 += o * sDW[160 + idx];
            p2 += o * sDW[320 + idx];
        }
#pragma unroll
        for (int off = 16; off > 0; off >>= 1) {
            p0 += __shfl_xor_sync(FULL, p0, off);
            p1 += __shfl_xor_sync(FULL, p1, off);
            p2 += __shfl_xor_sync(FULL, p2, off);
        }
        if (lane < 3) {
            float pv = (lane == 0) ? p0 : ((lane == 1) ? p1 : p2);
            pv += sDB[lane];
            out[(base + bi) * 3 + lane] = lrelu(pv);
        }
    }
}

extern "C" void kernel_launch(void* const* d_in, const int* in_sizes, int n_in,
                              void* d_out, int out_size) {
    const float* data  = (const float*)d_in[0];
    const float* w_ih0 = (const float*)d_in[1];
    const float* w_hh0 = (const float*)d_in[2];
    const float* b_ih0 = (const float*)d_in[3];
    const float* b_hh0 = (const float*)d_in[4];
    const float* g0    = (const float*)d_in[5];
    const float* be0   = (const float*)d_in[6];
    const float* w_ih1 = (const float*)d_in[7];
    const float* w_hh1 = (const float*)d_in[8];
    const float* b_ih1 = (const float*)d_in[9];
    const float* b_hh1 = (const float*)d_in[10];
    const float* g1    = (const float*)d_in[11];
    const float* be1   = (const float*)d_in[12];
    const float* dw    = (const float*)d_in[13];
    const float* db    = (const float*)d_in[14];
    float* out = (float*)d_out;

    cudaFuncSetAttribute(reslstm_kernel,
                         cudaFuncAttributeMaxDynamicSharedMemorySize, SMEM_BYTES);

    prep_kernel<<<12, 256>>>(w_ih0, w_ih1);

    int grid = B_TOTAL / (NWARP * NB);   // 8192
    reslstm_kernel<<<grid, NT, SMEM_BYTES>>>(
        data, w_hh0, b_ih0, b_hh0, g0, be0,
        w_hh1, b_ih1, b_hh1, g1, be1, dw, db, out);
}